// round 13
// baseline (speedup 1.0000x reference)
#include <cuda_runtime.h>
#include <cuda_bf16.h>

#define BN 8192
#define EN 8
#define HN 128
#define TS 128
#define NT (BN / TS)                 // 64 tiles per dim
#define NPAIR (NT * (NT + 1) / 2)    // 2080 upper-triangular tile pairs
#define GRID_PAIR 296                // 2 CTAs/SM (512 thr), one wave
#define PREP_BLKS (BN / 8)           // 1024

// ---------------- device scratch -------------------------------------------
// Fragment-linear bf16 tile images (UNCHANGED from R12 — validated layout).
// One "block" = 512 B = one warp fragment group: lane l holds 16 B at l*16.
//  A image: block (tile, mt 0..7, s16 0..7)  [m16n8k16 A-frag]
//  B image: block (tile, pnt 0..7, s16 0..7) [two n8 B-frags packed]
__device__ __align__(1024) unsigned char g_A[NT * 64 * 512];   // 2 MB
__device__ __align__(1024) unsigned char g_B[NT * 64 * 512];   // 2 MB
// KL operand images, same fragment layouts, single s16:
//   X_i = [logp_i - a_i (8), p_i (8)] (A-frag), Y_j = [p_j (8), logp_j - a_j (8)] (B-frag)
//   X_i . Y_j = -(kl(i,j) + kl(j,i))   (uses sum_e p = 1)
__device__ __align__(1024) unsigned char g_Xf[NT * 8 * 512];   // 256 KB
__device__ __align__(1024) unsigned char g_Yf[NT * 8 * 512];   // 256 KB
// prep per-block partials (written unconditionally -> no zeroing kernel)
__device__ double g_pp_task[PREP_BLKS], g_pp_eff[PREP_BLKS], g_pp_ent[PREP_BLKS];
__device__ float  g_pp_us[PREP_BLKS * EN];
// pair per-CTA partials + never-reset ticket (modular check is replay-safe)
__device__ double g_pair_kl[GRID_PAIR];
__device__ double g_pair_cnt[GRID_PAIR];
__device__ unsigned g_ticket;

// ---------------- PTX helpers ----------------------------------------------
__device__ __forceinline__ void mma16816(float* d, const unsigned* a, const unsigned* b) {
    asm volatile(
        "mma.sync.aligned.m16n8k16.row.col.f32.bf16.bf16.f32 "
        "{%0,%1,%2,%3}, {%4,%5,%6,%7}, {%8,%9}, {%0,%1,%2,%3};"
        : "+f"(d[0]), "+f"(d[1]), "+f"(d[2]), "+f"(d[3])
        : "r"(a[0]), "r"(a[1]), "r"(a[2]), "r"(a[3]), "r"(b[0]), "r"(b[1]));
}
__device__ __forceinline__ unsigned pkbf(float a, float b) {
    return (unsigned)__bfloat16_as_ushort(__float2bfloat16_rn(a)) |
           ((unsigned)__bfloat16_as_ushort(__float2bfloat16_rn(b)) << 16);
}
__device__ __forceinline__ double wredd(double v) {
#pragma unroll
    for (int o = 16; o > 0; o >>= 1) v += __shfl_xor_sync(0xffffffffu, v, o);
    return v;
}

// ---------------- per-row preprocessing + cheap loss partials ---------------
__global__ __launch_bounds__(256) void prep_kernel(
    const float* __restrict__ logits,
    const int* __restrict__ targets,
    const float* __restrict__ rp,
    const float* __restrict__ emb) {
    int warp = threadIdx.x >> 5, lane = threadIdx.x & 31;
    int row = blockIdx.x * 8 + warp;
    __shared__ float  s_us[EN];
    __shared__ double s_task[8], s_eff[8], s_ent[8];
    if (threadIdx.x < EN) s_us[threadIdx.x] = 0.f;
    __syncthreads();

    // normalize embedding row (float4 per lane = 4 consecutive k-cols)
    float4 v = *(const float4*)(emb + (size_t)row * HN + lane * 4);
    float ss = v.x * v.x + v.y * v.y + v.z * v.z + v.w * v.w;
#pragma unroll
    for (int o = 16; o > 0; o >>= 1) ss += __shfl_xor_sync(0xffffffffu, ss, o);
    float inv = rsqrtf(ss);
    float4 w = make_float4(v.x * inv, v.y * inv, v.z * inv, v.w * inv);

    // write bf16 fragment-linear sim images (A-frag + B-frag)
    {
        int lr   = row & (TS - 1);
        int tile = row >> 7;
        int c0   = lane * 4;                 // cols c0..c0+3, same s16 & khalf
        int s16  = c0 >> 4;
        int kh   = (c0 >> 3) & 1;
        int l0   = ((lr & 7) << 2) | ((c0 & 7) >> 1);   // lanes l0, l0+1
        unsigned w0 = pkbf(w.x, w.y), w1 = pkbf(w.z, w.w);
        int mt = lr >> 4, r8 = (lr >> 3) & 1;
        unsigned baseA = (unsigned)((tile * 64 + mt * 8 + s16) << 9);
        unsigned regA  = (unsigned)(((kh << 1) | r8) << 2);
        *(unsigned*)(g_A + baseA + l0 * 16 + regA)       = w0;
        *(unsigned*)(g_A + baseA + (l0 + 1) * 16 + regA) = w1;
        unsigned baseB = (unsigned)((tile * 64 + mt * 8 + s16) << 9); // pnt==mt
        unsigned innB  = (unsigned)(r8 * 8 + kh * 4);    // ntl==r8
        *(unsigned*)(g_B + baseB + l0 * 16 + innB)       = w0;
        *(unsigned*)(g_B + baseB + (l0 + 1) * 16 + innB) = w1;
    }

    // routing-prob softmax over E=8
    float r = (lane < EN) ? rp[row * EN + lane] : -3.0e38f;
    float m = r;
#pragma unroll
    for (int o = 4; o > 0; o >>= 1) m = fmaxf(m, __shfl_xor_sync(0xffffffffu, m, o));
    float ex = (lane < EN) ? expf(r - m) : 0.f;
    float es = ex;
#pragma unroll
    for (int o = 4; o > 0; o >>= 1) es += __shfl_xor_sync(0xffffffffu, es, o);
    float lse = m + logf(es);
    float lp = r - lse;
    float p  = expf(lp);

    float av  = (lane < EN) ? p * lp : 0.f;
    float evv = (lane < EN && r < 0.1f) ? r : 0.f;
    float nv  = (lane < EN) ? r * logf(r + 1e-8f) : 0.f;
#pragma unroll
    for (int o = 4; o > 0; o >>= 1) {
        av  += __shfl_xor_sync(0xffffffffu, av, o);
        evv += __shfl_xor_sync(0xffffffffu, evv, o);
        nv  += __shfl_xor_sync(0xffffffffu, nv, o);
    }

    // write fragment-linear X/Y KL images (lane e = col-pair index 0..7)
    {
        float l0v = __shfl_sync(0xffffffffu, lp, (lane & 3) * 2);
        float l1v = __shfl_sync(0xffffffffu, lp, (lane & 3) * 2 + 1);
        float p0v = __shfl_sync(0xffffffffu, p,  (lane & 3) * 2);
        float p1v = __shfl_sync(0xffffffffu, p,  (lane & 3) * 2 + 1);
        if (lane < 8) {
            int e = lane;
            unsigned lw = pkbf(l0v - av, l1v - av);
            unsigned pw = pkbf(p0v, p1v);
            unsigned Xw = (e < 4) ? lw : pw;
            unsigned Yw = (e < 4) ? pw : lw;
            int lr = row & (TS - 1), tile = row >> 7;
            int mt = lr >> 4, r8 = (lr >> 3) & 1, kh = e >> 2;
            int lX = ((lr & 7) << 2) | (e & 3);
            unsigned base = (unsigned)((tile * 8 + mt) << 9);
            *(unsigned*)(g_Xf + base + lX * 16 + (((kh << 1) | r8) << 2)) = Xw;
            *(unsigned*)(g_Yf + base + lX * 16 + r8 * 8 + kh * 4)         = Yw;
        }
    }

    if (lane < EN) atomicAdd(&s_us[lane], r);
    if (lane == 0) {
        float l0 = logits[row * 3 + 0], l1 = logits[row * 3 + 1], l2 = logits[row * 3 + 2];
        float mm = fmaxf(l0, fmaxf(l1, l2));
        float lsm = mm + logf(expf(l0 - mm) + expf(l1 - mm) + expf(l2 - mm));
        int t = targets[row];
        float lt = (t == 0) ? l0 : ((t == 1) ? l1 : l2);
        s_task[warp] = (double)(lsm - lt);
        s_eff[warp]  = (double)evv;
        s_ent[warp]  = (double)nv;
    }
    __syncthreads();
    if (threadIdx.x == 0) {
        double a = 0, b = 0, c = 0;
        for (int i = 0; i < 8; i++) { a += s_task[i]; b += s_eff[i]; c += s_ent[i]; }
        g_pp_task[blockIdx.x] = a;
        g_pp_eff[blockIdx.x]  = b;
        g_pp_ent[blockIdx.x]  = c;
    }
    if (threadIdx.x < EN) g_pp_us[blockIdx.x * EN + threadIdx.x] = s_us[threadIdx.x];
}

// ---------------- pair kernel: 16 warps, 32x32 per warp, direct-LDG ---------
// 512 threads, 2 CTAs/SM -> 32 warps/SM (2x R12 occupancy). Warp (wid&3,
// wid>>2) owns m-rows (wid&3)*32..+32, n-cols (wid>>2)*32..+32: acc = 32
// floats, per s-iter 4 LDG.128 + 8 mma. No smem staging, no mainloop barriers.
// Epilogue: ONE 32-bit mask + ONE bf16 K=16 GEMM (X x Y^T = -(kl+kl')).
__global__ __launch_bounds__(512, 2) void pair_kernel(
    const float* __restrict__ temperature, float* __restrict__ out) {
    __shared__ float s_rk[16];
    __shared__ int   s_rc[16];
    __shared__ double s_fin[6][16];
    __shared__ int s_last;

    int tid  = threadIdx.x;
    int wid  = tid >> 5;
    int lane = tid & 31;

    int mt0 = (wid & 3) * 2;        // warp's first m16 block (of 8)
    int pn0 = (wid >> 2) * 2;       // warp's first pnt block (of 8)
    int mbase = mt0 * 16;
    int nbase = pn0 * 16;

    float kls = 0.f;
    int   cnt = 0;

    // decode first tile
    int ti = 0, rem = blockIdx.x;
    while (rem >= NT - ti) { rem -= NT - ti; ti++; }
    int tj = ti + rem;

    for (int t = blockIdx.x; t < NPAIR; t += GRID_PAIR) {
        bool diag = (ti == tj);
        int ti2 = ti, tj2 = tj;
        if (t + GRID_PAIR < NPAIR) {
            int a = 0, r2 = t + GRID_PAIR;
            while (r2 >= NT - a) { r2 -= NT - a; a++; }
            ti2 = a; tj2 = a + r2;
        }

        const uint4* Ab = (const uint4*)g_A + ((size_t)ti << 11) + lane;
        const uint4* Bb = (const uint4*)g_B + ((size_t)tj << 11) + lane;

        float acc[2][4][4];             // [mt][pnt*2+ntl][quad]
#pragma unroll
        for (int a = 0; a < 2; a++)
#pragma unroll
            for (int b = 0; b < 4; b++)
#pragma unroll
                for (int c = 0; c < 4; c++) acc[a][b][c] = 0.f;

#pragma unroll
        for (int s = 0; s < 8; s++) {
            uint4 a0 = __ldg(Ab + ((mt0 + 0) * 8 + s) * 32);
            uint4 a1 = __ldg(Ab + ((mt0 + 1) * 8 + s) * 32);
            uint4 b0 = __ldg(Bb + ((pn0 + 0) * 8 + s) * 32);
            uint4 b1 = __ldg(Bb + ((pn0 + 1) * 8 + s) * 32);
            const unsigned* af[2] = { (const unsigned*)&a0, (const unsigned*)&a1 };
            const unsigned* bp[2] = { (const unsigned*)&b0, (const unsigned*)&b1 };
#pragma unroll
            for (int mt = 0; mt < 2; mt++)
#pragma unroll
                for (int pnt = 0; pnt < 2; pnt++) {
                    mma16816(acc[mt][pnt * 2 + 0], af[mt], bp[pnt] + 0);
                    mma16816(acc[mt][pnt * 2 + 1], af[mt], bp[pnt] + 2);
                }
        }

        // ---- pack threshold mask: ONE 32-bit register per warp ----
        unsigned msk = 0;
        if (!diag) {
#pragma unroll
            for (int mt = 0; mt < 2; mt++)
#pragma unroll
                for (int nt = 0; nt < 4; nt++)
#pragma unroll
                    for (int q = 0; q < 4; q++)
                        msk |= (acc[mt][nt][q] > 0.8f ? 1u : 0u)
                               << (mt * 16 + nt * 4 + q);
            cnt += 2 * __popc(msk);
        } else {
#pragma unroll
            for (int mt = 0; mt < 2; mt++)
#pragma unroll
                for (int nt = 0; nt < 4; nt++)
#pragma unroll
                    for (int q = 0; q < 4; q++) {
                        int il = mbase + mt * 16 + (q >> 1) * 8 + (lane >> 2);
                        int jl = nbase + nt * 8 + (lane & 3) * 2 + (q & 1);
                        bool pass = (acc[mt][nt][q] > 0.8f) && (il != jl);
                        msk |= (pass ? 1u : 0u) << (mt * 16 + nt * 4 + q);
                    }
            cnt += __popc(msk);
        }

        // ---- ONE bf16 K=16 GEMM: D = X_i x Y_j^T = -(kl(i,j)+kl(j,i)) ----
#pragma unroll
        for (int a = 0; a < 2; a++)
#pragma unroll
            for (int b = 0; b < 4; b++)
#pragma unroll
                for (int c = 0; c < 4; c++) acc[a][b][c] = 0.f;
        {
            const uint4* Xb = (const uint4*)g_Xf + ((size_t)ti << 8) + lane;
            const uint4* Yb = (const uint4*)g_Yf + ((size_t)tj << 8) + lane;
            uint4 xa0 = __ldg(Xb + (mt0 + 0) * 32);
            uint4 xa1 = __ldg(Xb + (mt0 + 1) * 32);
            uint4 yb0 = __ldg(Yb + (pn0 + 0) * 32);
            uint4 yb1 = __ldg(Yb + (pn0 + 1) * 32);
            const unsigned* xf[2] = { (const unsigned*)&xa0, (const unsigned*)&xa1 };
            const unsigned* yp[2] = { (const unsigned*)&yb0, (const unsigned*)&yb1 };
#pragma unroll
            for (int mt = 0; mt < 2; mt++)
#pragma unroll
                for (int pnt = 0; pnt < 2; pnt++) {
                    mma16816(acc[mt][pnt * 2 + 0], xf[mt], yp[pnt] + 0);
                    mma16816(acc[mt][pnt * 2 + 1], xf[mt], yp[pnt] + 2);
                }
        }
        float S = 0.f;
#pragma unroll
        for (int mt = 0; mt < 2; mt++)
#pragma unroll
            for (int nt = 0; nt < 4; nt++)
#pragma unroll
                for (int q = 0; q < 4; q++)
                    S += ((msk >> (mt * 16 + nt * 4 + q)) & 1u) ? acc[mt][nt][q] : 0.f;
        kls -= diag ? 0.5f * S : S;    // D = -(kl sum); diag double-counts pairs

        ti = ti2; tj = tj2;
    }

    // ---- flush per-CTA partial ----
#pragma unroll
    for (int o = 16; o > 0; o >>= 1) {
        kls += __shfl_xor_sync(0xffffffffu, kls, o);
        cnt += __shfl_xor_sync(0xffffffffu, cnt, o);
    }
    if (lane == 0) { s_rk[wid] = kls; s_rc[wid] = cnt; }
    __syncthreads();
    if (tid == 0) {
        double K = 0, C = 0;
        for (int w = 0; w < 16; w++) { K += (double)s_rk[w]; C += (double)s_rc[w]; }
        g_pair_kl[blockIdx.x]  = K;
        g_pair_cnt[blockIdx.x] = C;
        __threadfence();
        unsigned old = atomicAdd(&g_ticket, 1u);
        s_last = ((old % GRID_PAIR) == GRID_PAIR - 1) ? 1 : 0;
    }
    __syncthreads();
    if (!s_last) return;
    __threadfence();

    // ---- last CTA: reduce all partials, compute final loss ----
    double K = 0, C = 0, Tk = 0, Ef = 0, Ent = 0;
    for (int i = tid; i < GRID_PAIR; i += 512) { K += g_pair_kl[i]; C += g_pair_cnt[i]; }
    for (int i = tid; i < PREP_BLKS; i += 512) {
        Tk += g_pp_task[i]; Ef += g_pp_eff[i]; Ent += g_pp_ent[i];
    }
    double Us = 0;                     // warps 0-7: warp w reduces expert w
    if (wid < 8)
        for (int i = lane; i < PREP_BLKS; i += 32) Us += (double)g_pp_us[i * EN + wid];

    K = wredd(K); C = wredd(C); Tk = wredd(Tk); Ef = wredd(Ef); Ent = wredd(Ent);
    Us = wredd(Us);
    if (lane == 0) {
        s_fin[0][wid] = K;  s_fin[1][wid] = C;  s_fin[2][wid] = Tk;
        s_fin[3][wid] = Ef; s_fin[4][wid] = Ent; s_fin[5][wid] = Us;
    }
    __syncthreads();
    if (tid == 0) {
        double k = 0, c = 0, tk = 0, ef = 0, en = 0;
        for (int w = 0; w < 16; w++) {
            k += s_fin[0][w]; c += s_fin[1][w]; tk += s_fin[2][w];
            ef += s_fin[3][w]; en += s_fin[4][w];
        }
        double u[EN], mu = 0.0;
        for (int e = 0; e < EN; e++) { u[e] = s_fin[5][e] / (double)BN; mu += u[e]; }
        mu /= (double)EN;
        double var = 0.0;
        for (int e = 0; e < EN; e++) var += (u[e] - mu) * (u[e] - mu);
        var /= (double)(EN - 1);
        double cons = (c > 0.0) ? 0.1 * (k / c) : 0.0;
        double tt = (double)temperature[0] - 1.0;
        double loss = tk / (double)BN
                    + 0.1 * var * (double)(EN * EN)
                    + 0.05 * ef / (double)BN
                    + cons
                    + 0.01 * en / (double)BN
                    + 0.01 * tt * tt;
        out[0] = (float)loss;
    }
}

// ---------------- launch -----------------------------------------------------
extern "C" void kernel_launch(void* const* d_in, const int* in_sizes, int n_in,
                              void* d_out, int out_size) {
    const float* logits  = (const float*)d_in[0];
    const int*   targets = (const int*)d_in[1];
    const float* rp      = (const float*)d_in[2];
    const float* emb     = (const float*)d_in[3];
    const float* temp    = (const float*)d_in[4];
    float* out = (float*)d_out;

    prep_kernel<<<PREP_BLKS, 256>>>(logits, targets, rp, emb);
    pair_kernel<<<GRID_PAIR, 512>>>(temp, out);
}

// round 15
// speedup vs baseline: 1.6857x; 1.6857x over previous
#include <cuda_runtime.h>
#include <cuda_bf16.h>

#define BN 8192
#define EN 8
#define HN 128
#define TS 128
#define NT (BN / TS)                 // 64 tiles per dim
#define NPAIR (NT * (NT + 1) / 2)    // 2080 upper-triangular tile pairs
#define GRID_PAIR 296                // 2 CTAs/SM, one wave
#define PREP_BLKS (BN / 8)           // 1024

// ---------------- device scratch -------------------------------------------
// Fragment-linear bf16 tile images (validated layout, canary-exact).
// One "block" = 512 B = one warp fragment group: lane l holds 16 B at l*16.
//  A image: block (tile, mt 0..7, s16 0..7)  [m16n8k16 A-frag]
//  B image: block (tile, pnt 0..7, s16 0..7) [two n8 B-frags packed]
__device__ __align__(1024) unsigned char g_A[NT * 64 * 512];   // 2 MB
__device__ __align__(1024) unsigned char g_B[NT * 64 * 512];   // 2 MB
// KL operand images, same fragment layouts, single s16:
//   X_i = [logp_i - a_i (8), p_i (8)] (A-frag), Y_j = [p_j (8), logp_j - a_j (8)] (B-frag)
//   X_i . Y_j = -(kl(i,j) + kl(j,i))   (uses sum_e p = 1)
__device__ __align__(1024) unsigned char g_Xf[NT * 8 * 512];   // 256 KB
__device__ __align__(1024) unsigned char g_Yf[NT * 8 * 512];   // 256 KB
// prep per-block partials (written unconditionally -> no zeroing kernel)
__device__ double g_pp_task[PREP_BLKS], g_pp_eff[PREP_BLKS], g_pp_ent[PREP_BLKS];
__device__ float  g_pp_us[PREP_BLKS * EN];
// pair per-CTA partials + never-reset ticket (modular check is replay-safe)
__device__ double g_pair_kl[GRID_PAIR];
__device__ double g_pair_cnt[GRID_PAIR];
__device__ unsigned g_ticket;

// ---------------- PTX helpers ----------------------------------------------
__device__ __forceinline__ void mma16816(float* d, const unsigned* a, const unsigned* b) {
    asm volatile(
        "mma.sync.aligned.m16n8k16.row.col.f32.bf16.bf16.f32 "
        "{%0,%1,%2,%3}, {%4,%5,%6,%7}, {%8,%9}, {%0,%1,%2,%3};"
        : "+f"(d[0]), "+f"(d[1]), "+f"(d[2]), "+f"(d[3])
        : "r"(a[0]), "r"(a[1]), "r"(a[2]), "r"(a[3]), "r"(b[0]), "r"(b[1]));
}
__device__ __forceinline__ unsigned pkbf(float a, float b) {
    return (unsigned)__bfloat16_as_ushort(__float2bfloat16_rn(a)) |
           ((unsigned)__bfloat16_as_ushort(__float2bfloat16_rn(b)) << 16);
}
__device__ __forceinline__ double wredd(double v) {
#pragma unroll
    for (int o = 16; o > 0; o >>= 1) v += __shfl_xor_sync(0xffffffffu, v, o);
    return v;
}

// ---------------- per-row preprocessing + cheap loss partials ---------------
__global__ __launch_bounds__(256) void prep_kernel(
    const float* __restrict__ logits,
    const int* __restrict__ targets,
    const float* __restrict__ rp,
    const float* __restrict__ emb) {
    int warp = threadIdx.x >> 5, lane = threadIdx.x & 31;
    int row = blockIdx.x * 8 + warp;
    __shared__ float  s_us[EN];
    __shared__ double s_task[8], s_eff[8], s_ent[8];
    if (threadIdx.x < EN) s_us[threadIdx.x] = 0.f;
    __syncthreads();

    // normalize embedding row (float4 per lane = 4 consecutive k-cols)
    float4 v = *(const float4*)(emb + (size_t)row * HN + lane * 4);
    float ss = v.x * v.x + v.y * v.y + v.z * v.z + v.w * v.w;
#pragma unroll
    for (int o = 16; o > 0; o >>= 1) ss += __shfl_xor_sync(0xffffffffu, ss, o);
    float inv = rsqrtf(ss);
    float4 w = make_float4(v.x * inv, v.y * inv, v.z * inv, v.w * inv);

    // write bf16 fragment-linear sim images (A-frag + B-frag)
    {
        int lr   = row & (TS - 1);
        int tile = row >> 7;
        int c0   = lane * 4;                 // cols c0..c0+3, same s16 & khalf
        int s16  = c0 >> 4;
        int kh   = (c0 >> 3) & 1;
        int l0   = ((lr & 7) << 2) | ((c0 & 7) >> 1);   // lanes l0, l0+1
        unsigned w0 = pkbf(w.x, w.y), w1 = pkbf(w.z, w.w);
        int mt = lr >> 4, r8 = (lr >> 3) & 1;
        unsigned baseA = (unsigned)((tile * 64 + mt * 8 + s16) << 9);
        unsigned regA  = (unsigned)(((kh << 1) | r8) << 2);
        *(unsigned*)(g_A + baseA + l0 * 16 + regA)       = w0;
        *(unsigned*)(g_A + baseA + (l0 + 1) * 16 + regA) = w1;
        unsigned baseB = (unsigned)((tile * 64 + mt * 8 + s16) << 9); // pnt==mt
        unsigned innB  = (unsigned)(r8 * 8 + kh * 4);    // ntl==r8
        *(unsigned*)(g_B + baseB + l0 * 16 + innB)       = w0;
        *(unsigned*)(g_B + baseB + (l0 + 1) * 16 + innB) = w1;
    }

    // routing-prob softmax over E=8
    float r = (lane < EN) ? rp[row * EN + lane] : -3.0e38f;
    float m = r;
#pragma unroll
    for (int o = 4; o > 0; o >>= 1) m = fmaxf(m, __shfl_xor_sync(0xffffffffu, m, o));
    float ex = (lane < EN) ? expf(r - m) : 0.f;
    float es = ex;
#pragma unroll
    for (int o = 4; o > 0; o >>= 1) es += __shfl_xor_sync(0xffffffffu, es, o);
    float lse = m + logf(es);
    float lp = r - lse;
    float p  = expf(lp);

    float av  = (lane < EN) ? p * lp : 0.f;
    float evv = (lane < EN && r < 0.1f) ? r : 0.f;
    float nv  = (lane < EN) ? r * logf(r + 1e-8f) : 0.f;
#pragma unroll
    for (int o = 4; o > 0; o >>= 1) {
        av  += __shfl_xor_sync(0xffffffffu, av, o);
        evv += __shfl_xor_sync(0xffffffffu, evv, o);
        nv  += __shfl_xor_sync(0xffffffffu, nv, o);
    }

    // write fragment-linear X/Y KL images (lane e = col-pair index 0..7)
    {
        float l0v = __shfl_sync(0xffffffffu, lp, (lane & 3) * 2);
        float l1v = __shfl_sync(0xffffffffu, lp, (lane & 3) * 2 + 1);
        float p0v = __shfl_sync(0xffffffffu, p,  (lane & 3) * 2);
        float p1v = __shfl_sync(0xffffffffu, p,  (lane & 3) * 2 + 1);
        if (lane < 8) {
            int e = lane;
            unsigned lw = pkbf(l0v - av, l1v - av);
            unsigned pw = pkbf(p0v, p1v);
            unsigned Xw = (e < 4) ? lw : pw;
            unsigned Yw = (e < 4) ? pw : lw;
            int lr = row & (TS - 1), tile = row >> 7;
            int mt = lr >> 4, r8 = (lr >> 3) & 1, kh = e >> 2;
            int lX = ((lr & 7) << 2) | (e & 3);
            unsigned base = (unsigned)((tile * 8 + mt) << 9);
            *(unsigned*)(g_Xf + base + lX * 16 + (((kh << 1) | r8) << 2)) = Xw;
            *(unsigned*)(g_Yf + base + lX * 16 + r8 * 8 + kh * 4)         = Yw;
        }
    }

    if (lane < EN) atomicAdd(&s_us[lane], r);
    if (lane == 0) {
        float l0 = logits[row * 3 + 0], l1 = logits[row * 3 + 1], l2 = logits[row * 3 + 2];
        float mm = fmaxf(l0, fmaxf(l1, l2));
        float lsm = mm + logf(expf(l0 - mm) + expf(l1 - mm) + expf(l2 - mm));
        int t = targets[row];
        float lt = (t == 0) ? l0 : ((t == 1) ? l1 : l2);
        s_task[warp] = (double)(lsm - lt);
        s_eff[warp]  = (double)evv;
        s_ent[warp]  = (double)nv;
    }
    __syncthreads();
    if (threadIdx.x == 0) {
        double a = 0, b = 0, c = 0;
        for (int i = 0; i < 8; i++) { a += s_task[i]; b += s_eff[i]; c += s_ent[i]; }
        g_pp_task[blockIdx.x] = a;
        g_pp_eff[blockIdx.x]  = b;
        g_pp_ent[blockIdx.x]  = c;
    }
    if (threadIdx.x < EN) g_pp_us[blockIdx.x * EN + threadIdx.x] = s_us[threadIdx.x];
}

// ---------------- pair kernel: R12 geometry + SW-pipelined fragments --------
// 256 threads, 2 CTAs/SM; warp owns 32 m-rows x 64 n-cols (R12 geometry).
// Direct LDG.128 of fragment-linear images, DOUBLE-BUFFERED in registers:
// iteration s's mma block runs while s+1's 6 fragment loads are in flight.
// Epilogue: mask pack + ONE bf16 K=16 GEMM D = X x Y^T = -(kl+kl').
__global__ __launch_bounds__(256, 2) void pair_kernel(
    const float* __restrict__ temperature, float* __restrict__ out) {
    __shared__ float s_rk[8];
    __shared__ int   s_rc[8];
    __shared__ double s_fin[6][8];
    __shared__ int s_last;

    int tid  = threadIdx.x;
    int wid  = tid >> 5;
    int lane = tid & 31;

    int mt0 = (wid & 3) * 2;        // warp's first m16-tile (of 8)
    int pn0 = (wid >> 2) * 4;       // warp's first pnt block (of 8)
    int mbase = mt0 * 16;
    int nbase = pn0 * 16;

    float kls = 0.f;
    int   cnt = 0;

    // decode first tile
    int ti = 0, rem = blockIdx.x;
    while (rem >= NT - ti) { rem -= NT - ti; ti++; }
    int tj = ti + rem;

    for (int t = blockIdx.x; t < NPAIR; t += GRID_PAIR) {
        bool diag = (ti == tj);
        int ti2 = ti, tj2 = tj;
        if (t + GRID_PAIR < NPAIR) {
            int a = 0, r2 = t + GRID_PAIR;
            while (r2 >= NT - a) { r2 -= NT - a; a++; }
            ti2 = a; tj2 = a + r2;
        }

        const uint4* Ab = (const uint4*)g_A + ((size_t)ti << 11) + lane;
        const uint4* Bb = (const uint4*)g_B + ((size_t)tj << 11) + lane;

        float acc[2][8][4];
#pragma unroll
        for (int a = 0; a < 2; a++)
#pragma unroll
            for (int b = 0; b < 8; b++)
#pragma unroll
                for (int c = 0; c < 4; c++) acc[a][b][c] = 0.f;

        // double-buffered fragments: [buf][0..1]=A, [buf][2..5]=B
        uint4 fr[2][6];
        fr[0][0] = __ldg(Ab + ((mt0 + 0) * 8 + 0) * 32);
        fr[0][1] = __ldg(Ab + ((mt0 + 1) * 8 + 0) * 32);
        fr[0][2] = __ldg(Bb + ((pn0 + 0) * 8 + 0) * 32);
        fr[0][3] = __ldg(Bb + ((pn0 + 1) * 8 + 0) * 32);
        fr[0][4] = __ldg(Bb + ((pn0 + 2) * 8 + 0) * 32);
        fr[0][5] = __ldg(Bb + ((pn0 + 3) * 8 + 0) * 32);

#pragma unroll
        for (int s = 0; s < 8; s++) {
            int cur = s & 1, nxt = cur ^ 1;
            if (s < 7) {
                fr[nxt][0] = __ldg(Ab + ((mt0 + 0) * 8 + s + 1) * 32);
                fr[nxt][1] = __ldg(Ab + ((mt0 + 1) * 8 + s + 1) * 32);
                fr[nxt][2] = __ldg(Bb + ((pn0 + 0) * 8 + s + 1) * 32);
                fr[nxt][3] = __ldg(Bb + ((pn0 + 1) * 8 + s + 1) * 32);
                fr[nxt][4] = __ldg(Bb + ((pn0 + 2) * 8 + s + 1) * 32);
                fr[nxt][5] = __ldg(Bb + ((pn0 + 3) * 8 + s + 1) * 32);
            }
            const unsigned* af0 = (const unsigned*)&fr[cur][0];
            const unsigned* af1 = (const unsigned*)&fr[cur][1];
#pragma unroll
            for (int pnt = 0; pnt < 4; pnt++) {
                const unsigned* bp = (const unsigned*)&fr[cur][2 + pnt];
                mma16816(acc[0][pnt * 2 + 0], af0, bp + 0);
                mma16816(acc[0][pnt * 2 + 1], af0, bp + 2);
                mma16816(acc[1][pnt * 2 + 0], af1, bp + 0);
                mma16816(acc[1][pnt * 2 + 1], af1, bp + 2);
            }
        }

        // ---- pack threshold masks (diag branch hoisted) ----
        unsigned msk[2];
        if (!diag) {
#pragma unroll
            for (int mt = 0; mt < 2; mt++) {
                unsigned mw = 0;
#pragma unroll
                for (int nt = 0; nt < 8; nt++)
#pragma unroll
                    for (int q = 0; q < 4; q++)
                        mw |= (acc[mt][nt][q] > 0.8f ? 1u : 0u) << (nt * 4 + q);
                msk[mt] = mw;
            }
            cnt += 2 * (__popc(msk[0]) + __popc(msk[1]));
        } else {
#pragma unroll
            for (int mt = 0; mt < 2; mt++) {
                unsigned mw = 0;
#pragma unroll
                for (int nt = 0; nt < 8; nt++)
#pragma unroll
                    for (int q = 0; q < 4; q++) {
                        int il = mbase + mt * 16 + (q >> 1) * 8 + (lane >> 2);
                        int jl = nbase + nt * 8 + (lane & 3) * 2 + (q & 1);
                        bool pass = (acc[mt][nt][q] > 0.8f) && (il != jl);
                        mw |= (pass ? 1u : 0u) << (nt * 4 + q);
                    }
                msk[mt] = mw;
            }
            cnt += __popc(msk[0]) + __popc(msk[1]);
        }

        // ---- ONE bf16 K=16 GEMM: D = X_i x Y_j^T = -(kl(i,j)+kl(j,i)) ----
#pragma unroll
        for (int a = 0; a < 2; a++)
#pragma unroll
            for (int b = 0; b < 8; b++)
#pragma unroll
                for (int c = 0; c < 4; c++) acc[a][b][c] = 0.f;
        {
            const uint4* Xb = (const uint4*)g_Xf + ((size_t)ti << 8) + lane;
            const uint4* Yb = (const uint4*)g_Yf + ((size_t)tj << 8) + lane;
            uint4 xa0 = __ldg(Xb + (mt0 + 0) * 32);
            uint4 xa1 = __ldg(Xb + (mt0 + 1) * 32);
            uint4 yb0 = __ldg(Yb + (pn0 + 0) * 32);
            uint4 yb1 = __ldg(Yb + (pn0 + 1) * 32);
            uint4 yb2 = __ldg(Yb + (pn0 + 2) * 32);
            uint4 yb3 = __ldg(Yb + (pn0 + 3) * 32);
            const unsigned* xf0 = (const unsigned*)&xa0;
            const unsigned* xf1 = (const unsigned*)&xa1;
            const unsigned* yp[4] = { (const unsigned*)&yb0, (const unsigned*)&yb1,
                                      (const unsigned*)&yb2, (const unsigned*)&yb3 };
#pragma unroll
            for (int pnt = 0; pnt < 4; pnt++) {
                mma16816(acc[0][pnt * 2 + 0], xf0, yp[pnt] + 0);
                mma16816(acc[0][pnt * 2 + 1], xf0, yp[pnt] + 2);
                mma16816(acc[1][pnt * 2 + 0], xf1, yp[pnt] + 0);
                mma16816(acc[1][pnt * 2 + 1], xf1, yp[pnt] + 2);
            }
        }
        float S = 0.f;
#pragma unroll
        for (int mt = 0; mt < 2; mt++)
#pragma unroll
            for (int nt = 0; nt < 8; nt++)
#pragma unroll
                for (int q = 0; q < 4; q++)
                    S += ((msk[mt] >> (nt * 4 + q)) & 1u) ? acc[mt][nt][q] : 0.f;
        kls -= diag ? 0.5f * S : S;    // D = -(kl sum); diag double-counts pairs

        ti = ti2; tj = tj2;
    }

    // ---- flush per-CTA partial ----
#pragma unroll
    for (int o = 16; o > 0; o >>= 1) {
        kls += __shfl_xor_sync(0xffffffffu, kls, o);
        cnt += __shfl_xor_sync(0xffffffffu, cnt, o);
    }
    if (lane == 0) { s_rk[wid] = kls; s_rc[wid] = cnt; }
    __syncthreads();
    if (tid == 0) {
        double K = 0, C = 0;
        for (int w = 0; w < 8; w++) { K += (double)s_rk[w]; C += (double)s_rc[w]; }
        g_pair_kl[blockIdx.x]  = K;
        g_pair_cnt[blockIdx.x] = C;
        __threadfence();
        unsigned old = atomicAdd(&g_ticket, 1u);
        s_last = ((old % GRID_PAIR) == GRID_PAIR - 1) ? 1 : 0;
    }
    __syncthreads();
    if (!s_last) return;
    __threadfence();

    // ---- last CTA: reduce all partials, compute final loss ----
    double K = 0, C = 0, Tk = 0, Ef = 0, Ent = 0;
    for (int i = tid; i < GRID_PAIR; i += 256) { K += g_pair_kl[i]; C += g_pair_cnt[i]; }
    for (int i = tid; i < PREP_BLKS; i += 256) {
        Tk += g_pp_task[i]; Ef += g_pp_eff[i]; Ent += g_pp_ent[i];
    }
    double Us = 0;                     // warp w reduces expert w
    for (int i = lane; i < PREP_BLKS; i += 32) Us += (double)g_pp_us[i * EN + wid];

    K = wredd(K); C = wredd(C); Tk = wredd(Tk); Ef = wredd(Ef); Ent = wredd(Ent);
    Us = wredd(Us);
    if (lane == 0) {
        s_fin[0][wid] = K;  s_fin[1][wid] = C;  s_fin[2][wid] = Tk;
        s_fin[3][wid] = Ef; s_fin[4][wid] = Ent; s_fin[5][wid] = Us;
    }
    __syncthreads();
    if (tid == 0) {
        double k = 0, c = 0, tk = 0, ef = 0, en = 0;
        for (int w = 0; w < 8; w++) {
            k += s_fin[0][w]; c += s_fin[1][w]; tk += s_fin[2][w];
            ef += s_fin[3][w]; en += s_fin[4][w];
        }
        double u[EN], mu = 0.0;
        for (int e = 0; e < EN; e++) { u[e] = s_fin[5][e] / (double)BN; mu += u[e]; }
        mu /= (double)EN;
        double var = 0.0;
        for (int e = 0; e < EN; e++) var += (u[e] - mu) * (u[e] - mu);
        var /= (double)(EN - 1);
        double cons = (c > 0.0) ? 0.1 * (k / c) : 0.0;
        double tt = (double)temperature[0] - 1.0;
        double loss = tk / (double)BN
                    + 0.1 * var * (double)(EN * EN)
                    + 0.05 * ef / (double)BN
                    + cons
                    + 0.01 * en / (double)BN
                    + 0.01 * tt * tt;
        out[0] = (float)loss;
    }
}

// ---------------- launch -----------------------------------------------------
extern "C" void kernel_launch(void* const* d_in, const int* in_sizes, int n_in,
                              void* d_out, int out_size) {
    const float* logits  = (const float*)d_in[0];
    const int*   targets = (const int*)d_in[1];
    const float* rp      = (const float*)d_in[2];
    const float* emb     = (const float*)d_in[3];
    const float* temp    = (const float*)d_in[4];
    float* out = (float*)d_out;

    prep_kernel<<<PREP_BLKS, 256>>>(logits, targets, rp, emb);
    pair_kernel<<<GRID_PAIR, 256>>>(temp, out);
}

// round 16
// speedup vs baseline: 1.6867x; 1.0006x over previous
#include <cuda_runtime.h>
#include <cuda_fp16.h>

#define BN 8192
#define EN 8
#define HN 128
#define TS 128
#define NT (BN / TS)                 // 64 tiles per dim
#define NPAIR (NT * (NT + 1) / 2)    // 2080 upper-triangular tile pairs
#define GRID_PAIR 444                // 3 CTAs/SM, one wave
#define PREP_BLKS (BN / 8)           // 1024

// ---------------- device scratch -------------------------------------------
// Fragment-linear fp16 tile images (same geometry as validated bf16 layout).
// One "block" = 512 B = one warp fragment group: lane l holds 16 B at l*16.
//  A image: block (tile, mt 0..7, s16 0..7)  [m16n8k16 A-frag]
//  B image: block (tile, pnt 0..7, s16 0..7) [two n8 B-frags packed]
__device__ __align__(1024) unsigned char g_A[NT * 64 * 512];   // 2 MB
__device__ __align__(1024) unsigned char g_B[NT * 64 * 512];   // 2 MB
// KL operand images, same fragment layouts, single s16:
//   X_i = [logp_i - a_i (8), p_i (8)] (A-frag), Y_j = [p_j (8), logp_j - a_j (8)] (B-frag)
//   X_i . Y_j = -(kl(i,j) + kl(j,i))   (uses sum_e p = 1)
__device__ __align__(1024) unsigned char g_Xf[NT * 8 * 512];   // 256 KB
__device__ __align__(1024) unsigned char g_Yf[NT * 8 * 512];   // 256 KB
// prep per-block partials (written unconditionally -> no zeroing kernel)
__device__ double g_pp_task[PREP_BLKS], g_pp_eff[PREP_BLKS], g_pp_ent[PREP_BLKS];
__device__ float  g_pp_us[PREP_BLKS * EN];
// pair per-CTA partials + never-reset ticket (modular check is replay-safe)
__device__ double g_pair_kl[GRID_PAIR];
__device__ double g_pair_cnt[GRID_PAIR];
__device__ unsigned g_ticket;

// ---------------- PTX helpers ----------------------------------------------
// f16 x f16 -> f16 accumulate: D/C = 2 regs (4 halves: q0,q1 | q2,q3)
__device__ __forceinline__ void mmah(unsigned* d, const unsigned* a, const unsigned* b) {
    asm volatile(
        "mma.sync.aligned.m16n8k16.row.col.f16.f16.f16.f16 "
        "{%0,%1}, {%2,%3,%4,%5}, {%6,%7}, {%0,%1};"
        : "+r"(d[0]), "+r"(d[1])
        : "r"(a[0]), "r"(a[1]), "r"(a[2]), "r"(a[3]), "r"(b[0]), "r"(b[1]));
}
__device__ __forceinline__ unsigned pkhf(float a, float b) {
    return (unsigned)__half_as_ushort(__float2half_rn(a)) |
           ((unsigned)__half_as_ushort(__float2half_rn(b)) << 16);
}
__device__ __forceinline__ float2 h2f(unsigned u) {
    return __half22float2(*reinterpret_cast<const half2*>(&u));
}
__device__ __forceinline__ double wredd(double v) {
#pragma unroll
    for (int o = 16; o > 0; o >>= 1) v += __shfl_xor_sync(0xffffffffu, v, o);
    return v;
}

// ---------------- per-row preprocessing + cheap loss partials ---------------
__global__ __launch_bounds__(256) void prep_kernel(
    const float* __restrict__ logits,
    const int* __restrict__ targets,
    const float* __restrict__ rp,
    const float* __restrict__ emb) {
    int warp = threadIdx.x >> 5, lane = threadIdx.x & 31;
    int row = blockIdx.x * 8 + warp;
    __shared__ float  s_us[EN];
    __shared__ double s_task[8], s_eff[8], s_ent[8];
    if (threadIdx.x < EN) s_us[threadIdx.x] = 0.f;
    __syncthreads();

    // normalize embedding row (float4 per lane = 4 consecutive k-cols)
    float4 v = *(const float4*)(emb + (size_t)row * HN + lane * 4);
    float ss = v.x * v.x + v.y * v.y + v.z * v.z + v.w * v.w;
#pragma unroll
    for (int o = 16; o > 0; o >>= 1) ss += __shfl_xor_sync(0xffffffffu, ss, o);
    float inv = rsqrtf(ss);
    float4 w = make_float4(v.x * inv, v.y * inv, v.z * inv, v.w * inv);

    // write fp16 fragment-linear sim images (A-frag + B-frag)
    {
        int lr   = row & (TS - 1);
        int tile = row >> 7;
        int c0   = lane * 4;                 // cols c0..c0+3, same s16 & khalf
        int s16  = c0 >> 4;
        int kh   = (c0 >> 3) & 1;
        int l0   = ((lr & 7) << 2) | ((c0 & 7) >> 1);   // lanes l0, l0+1
        unsigned w0 = pkhf(w.x, w.y), w1 = pkhf(w.z, w.w);
        int mt = lr >> 4, r8 = (lr >> 3) & 1;
        unsigned baseA = (unsigned)((tile * 64 + mt * 8 + s16) << 9);
        unsigned regA  = (unsigned)(((kh << 1) | r8) << 2);
        *(unsigned*)(g_A + baseA + l0 * 16 + regA)       = w0;
        *(unsigned*)(g_A + baseA + (l0 + 1) * 16 + regA) = w1;
        unsigned baseB = (unsigned)((tile * 64 + mt * 8 + s16) << 9); // pnt==mt
        unsigned innB  = (unsigned)(r8 * 8 + kh * 4);    // ntl==r8
        *(unsigned*)(g_B + baseB + l0 * 16 + innB)       = w0;
        *(unsigned*)(g_B + baseB + (l0 + 1) * 16 + innB) = w1;
    }

    // routing-prob softmax over E=8
    float r = (lane < EN) ? rp[row * EN + lane] : -3.0e38f;
    float m = r;
#pragma unroll
    for (int o = 4; o > 0; o >>= 1) m = fmaxf(m, __shfl_xor_sync(0xffffffffu, m, o));
    float ex = (lane < EN) ? expf(r - m) : 0.f;
    float es = ex;
#pragma unroll
    for (int o = 4; o > 0; o >>= 1) es += __shfl_xor_sync(0xffffffffu, es, o);
    float lse = m + logf(es);
    float lp = r - lse;
    float p  = expf(lp);

    float av  = (lane < EN) ? p * lp : 0.f;
    float evv = (lane < EN && r < 0.1f) ? r : 0.f;
    float nv  = (lane < EN) ? r * logf(r + 1e-8f) : 0.f;
#pragma unroll
    for (int o = 4; o > 0; o >>= 1) {
        av  += __shfl_xor_sync(0xffffffffu, av, o);
        evv += __shfl_xor_sync(0xffffffffu, evv, o);
        nv  += __shfl_xor_sync(0xffffffffu, nv, o);
    }

    // write fragment-linear X/Y KL images (lane e = col-pair index 0..7)
    {
        float l0v = __shfl_sync(0xffffffffu, lp, (lane & 3) * 2);
        float l1v = __shfl_sync(0xffffffffu, lp, (lane & 3) * 2 + 1);
        float p0v = __shfl_sync(0xffffffffu, p,  (lane & 3) * 2);
        float p1v = __shfl_sync(0xffffffffu, p,  (lane & 3) * 2 + 1);
        if (lane < 8) {
            int e = lane;
            unsigned lw = pkhf(l0v - av, l1v - av);
            unsigned pw = pkhf(p0v, p1v);
            unsigned Xw = (e < 4) ? lw : pw;
            unsigned Yw = (e < 4) ? pw : lw;
            int lr = row & (TS - 1), tile = row >> 7;
            int mt = lr >> 4, r8 = (lr >> 3) & 1, kh = e >> 2;
            int lX = ((lr & 7) << 2) | (e & 3);
            unsigned base = (unsigned)((tile * 8 + mt) << 9);
            *(unsigned*)(g_Xf + base + lX * 16 + (((kh << 1) | r8) << 2)) = Xw;
            *(unsigned*)(g_Yf + base + lX * 16 + r8 * 8 + kh * 4)         = Yw;
        }
    }

    if (lane < EN) atomicAdd(&s_us[lane], r);
    if (lane == 0) {
        float l0 = logits[row * 3 + 0], l1 = logits[row * 3 + 1], l2 = logits[row * 3 + 2];
        float mm = fmaxf(l0, fmaxf(l1, l2));
        float lsm = mm + logf(expf(l0 - mm) + expf(l1 - mm) + expf(l2 - mm));
        int t = targets[row];
        float lt = (t == 0) ? l0 : ((t == 1) ? l1 : l2);
        s_task[warp] = (double)(lsm - lt);
        s_eff[warp]  = (double)evv;
        s_ent[warp]  = (double)nv;
    }
    __syncthreads();
    if (threadIdx.x == 0) {
        double a = 0, b = 0, c = 0;
        for (int i = 0; i < 8; i++) { a += s_task[i]; b += s_eff[i]; c += s_ent[i]; }
        g_pp_task[blockIdx.x] = a;
        g_pp_eff[blockIdx.x]  = b;
        g_pp_ent[blockIdx.x]  = c;
    }
    if (threadIdx.x < EN) g_pp_us[blockIdx.x * EN + threadIdx.x] = s_us[threadIdx.x];
}

// ---------------- pair kernel: fp16 acc, 3 CTAs/SM, direct-LDG --------------
// 256 threads, 3 CTAs/SM (24 warps/SM). Warp owns 32 m-rows x 64 n-cols.
// f16 accumulators (16 regs) + double-buffered fragments; regs fit the
// (256,3) 85-reg cap. Epilogue: mask pack from f16x2 + ONE f16 K=16 GEMM
// (X x Y^T = -(kl+kl')), fold in fp32.
__global__ __launch_bounds__(256, 3) void pair_kernel(
    const float* __restrict__ temperature, float* __restrict__ out) {
    __shared__ float s_rk[8];
    __shared__ int   s_rc[8];
    __shared__ double s_fin[6][8];
    __shared__ int s_last;

    int tid  = threadIdx.x;
    int wid  = tid >> 5;
    int lane = tid & 31;

    int mt0 = (wid & 3) * 2;        // warp's first m16-tile (of 8)
    int pn0 = (wid >> 2) * 4;       // warp's first pnt block (of 8)
    int mbase = mt0 * 16;
    int nbase = pn0 * 16;

    float kls = 0.f;
    int   cnt = 0;

    // decode first tile
    int ti = 0, rem = blockIdx.x;
    while (rem >= NT - ti) { rem -= NT - ti; ti++; }
    int tj = ti + rem;

    for (int t = blockIdx.x; t < NPAIR; t += GRID_PAIR) {
        bool diag = (ti == tj);
        int ti2 = ti, tj2 = tj;
        if (t + GRID_PAIR < NPAIR) {
            int a = 0, r2 = t + GRID_PAIR;
            while (r2 >= NT - a) { r2 -= NT - a; a++; }
            ti2 = a; tj2 = a + r2;
        }

        const uint4* Ab = (const uint4*)g_A + ((size_t)ti << 11) + lane;
        const uint4* Bb = (const uint4*)g_B + ((size_t)tj << 11) + lane;

        unsigned acc[2][8][2];          // f16x2 accumulators
#pragma unroll
        for (int a = 0; a < 2; a++)
#pragma unroll
            for (int b = 0; b < 8; b++) { acc[a][b][0] = 0u; acc[a][b][1] = 0u; }

        // double-buffered fragments: [buf][0..1]=A, [buf][2..5]=B
        uint4 fr[2][6];
        fr[0][0] = __ldg(Ab + ((mt0 + 0) * 8 + 0) * 32);
        fr[0][1] = __ldg(Ab + ((mt0 + 1) * 8 + 0) * 32);
        fr[0][2] = __ldg(Bb + ((pn0 + 0) * 8 + 0) * 32);
        fr[0][3] = __ldg(Bb + ((pn0 + 1) * 8 + 0) * 32);
        fr[0][4] = __ldg(Bb + ((pn0 + 2) * 8 + 0) * 32);
        fr[0][5] = __ldg(Bb + ((pn0 + 3) * 8 + 0) * 32);

#pragma unroll
        for (int s = 0; s < 8; s++) {
            int cur = s & 1, nxt = cur ^ 1;
            if (s < 7) {
                fr[nxt][0] = __ldg(Ab + ((mt0 + 0) * 8 + s + 1) * 32);
                fr[nxt][1] = __ldg(Ab + ((mt0 + 1) * 8 + s + 1) * 32);
                fr[nxt][2] = __ldg(Bb + ((pn0 + 0) * 8 + s + 1) * 32);
                fr[nxt][3] = __ldg(Bb + ((pn0 + 1) * 8 + s + 1) * 32);
                fr[nxt][4] = __ldg(Bb + ((pn0 + 2) * 8 + s + 1) * 32);
                fr[nxt][5] = __ldg(Bb + ((pn0 + 3) * 8 + s + 1) * 32);
            }
            const unsigned* af0 = (const unsigned*)&fr[cur][0];
            const unsigned* af1 = (const unsigned*)&fr[cur][1];
#pragma unroll
            for (int pnt = 0; pnt < 4; pnt++) {
                const unsigned* bp = (const unsigned*)&fr[cur][2 + pnt];
                mmah(acc[0][pnt * 2 + 0], af0, bp + 0);
                mmah(acc[0][pnt * 2 + 1], af0, bp + 2);
                mmah(acc[1][pnt * 2 + 0], af1, bp + 0);
                mmah(acc[1][pnt * 2 + 1], af1, bp + 2);
            }
        }

        // ---- pack threshold masks from f16x2 accumulators ----
        unsigned msk[2];
        if (!diag) {
#pragma unroll
            for (int mt = 0; mt < 2; mt++) {
                unsigned mw = 0;
#pragma unroll
                for (int nt = 0; nt < 8; nt++)
#pragma unroll
                    for (int rr = 0; rr < 2; rr++) {
                        float2 f = h2f(acc[mt][nt][rr]);
                        mw |= (f.x > 0.8f ? 1u : 0u) << (nt * 4 + rr * 2 + 0);
                        mw |= (f.y > 0.8f ? 1u : 0u) << (nt * 4 + rr * 2 + 1);
                    }
                msk[mt] = mw;
            }
            cnt += 2 * (__popc(msk[0]) + __popc(msk[1]));
        } else {
#pragma unroll
            for (int mt = 0; mt < 2; mt++) {
                unsigned mw = 0;
#pragma unroll
                for (int nt = 0; nt < 8; nt++)
#pragma unroll
                    for (int rr = 0; rr < 2; rr++) {
                        float2 f = h2f(acc[mt][nt][rr]);
                        int il = mbase + mt * 16 + rr * 8 + (lane >> 2);
                        int jl0 = nbase + nt * 8 + (lane & 3) * 2;
                        bool p0 = (f.x > 0.8f) && (il != jl0);
                        bool p1 = (f.y > 0.8f) && (il != jl0 + 1);
                        mw |= (p0 ? 1u : 0u) << (nt * 4 + rr * 2 + 0);
                        mw |= (p1 ? 1u : 0u) << (nt * 4 + rr * 2 + 1);
                    }
                msk[mt] = mw;
            }
            cnt += __popc(msk[0]) + __popc(msk[1]);
        }

        // ---- ONE f16 K=16 GEMM: D = X_i x Y_j^T = -(kl(i,j)+kl(j,i)) ----
#pragma unroll
        for (int a = 0; a < 2; a++)
#pragma unroll
            for (int b = 0; b < 8; b++) { acc[a][b][0] = 0u; acc[a][b][1] = 0u; }
        {
            const uint4* Xb = (const uint4*)g_Xf + ((size_t)ti << 8) + lane;
            const uint4* Yb = (const uint4*)g_Yf + ((size_t)tj << 8) + lane;
            uint4 xa0 = __ldg(Xb + (mt0 + 0) * 32);
            uint4 xa1 = __ldg(Xb + (mt0 + 1) * 32);
            uint4 yb0 = __ldg(Yb + (pn0 + 0) * 32);
            uint4 yb1 = __ldg(Yb + (pn0 + 1) * 32);
            uint4 yb2 = __ldg(Yb + (pn0 + 2) * 32);
            uint4 yb3 = __ldg(Yb + (pn0 + 3) * 32);
            const unsigned* xf0 = (const unsigned*)&xa0;
            const unsigned* xf1 = (const unsigned*)&xa1;
            const unsigned* yp[4] = { (const unsigned*)&yb0, (const unsigned*)&yb1,
                                      (const unsigned*)&yb2, (const unsigned*)&yb3 };
#pragma unroll
            for (int pnt = 0; pnt < 4; pnt++) {
                mmah(acc[0][pnt * 2 + 0], xf0, yp[pnt] + 0);
                mmah(acc[0][pnt * 2 + 1], xf0, yp[pnt] + 2);
                mmah(acc[1][pnt * 2 + 0], xf1, yp[pnt] + 0);
                mmah(acc[1][pnt * 2 + 1], xf1, yp[pnt] + 2);
            }
        }
        float S = 0.f;
#pragma unroll
        for (int mt = 0; mt < 2; mt++)
#pragma unroll
            for (int nt = 0; nt < 8; nt++)
#pragma unroll
                for (int rr = 0; rr < 2; rr++) {
                    float2 f = h2f(acc[mt][nt][rr]);
                    if ((msk[mt] >> (nt * 4 + rr * 2 + 0)) & 1u) S += f.x;
                    if ((msk[mt] >> (nt * 4 + rr * 2 + 1)) & 1u) S += f.y;
                }
        kls -= diag ? 0.5f * S : S;    // D = -(kl sum); diag double-counts pairs

        ti = ti2; tj = tj2;
    }

    // ---- flush per-CTA partial ----
#pragma unroll
    for (int o = 16; o > 0; o >>= 1) {
        kls += __shfl_xor_sync(0xffffffffu, kls, o);
        cnt += __shfl_xor_sync(0xffffffffu, cnt, o);
    }
    if (lane == 0) { s_rk[wid] = kls; s_rc[wid] = cnt; }
    __syncthreads();
    if (tid == 0) {
        double K = 0, C = 0;
        for (int w = 0; w < 8; w++) { K += (double)s_rk[w]; C += (double)s_rc[w]; }
        g_pair_kl[blockIdx.x]  = K;
        g_pair_cnt[blockIdx.x] = C;
        __threadfence();
        unsigned old = atomicAdd(&g_ticket, 1u);
        s_last = ((old % GRID_PAIR) == GRID_PAIR - 1) ? 1 : 0;
    }
    __syncthreads();
    if (!s_last) return;
    __threadfence();

    // ---- last CTA: reduce all partials, compute final loss ----
    double K = 0, C = 0, Tk = 0, Ef = 0, Ent = 0;
    for (int i = tid; i < GRID_PAIR; i += 256) { K += g_pair_kl[i]; C += g_pair_cnt[i]; }
    for (int i = tid; i < PREP_BLKS; i += 256) {
        Tk += g_pp_task[i]; Ef += g_pp_eff[i]; Ent += g_pp_ent[i];
    }
    double Us = 0;                     // warp w reduces expert w
    for (int i = lane; i < PREP_BLKS; i += 32) Us += (double)g_pp_us[i * EN + wid];

    K = wredd(K); C = wredd(C); Tk = wredd(Tk); Ef = wredd(Ef); Ent = wredd(Ent);
    Us = wredd(Us);
    if (lane == 0) {
        s_fin[0][wid] = K;  s_fin[1][wid] = C;  s_fin[2][wid] = Tk;
        s_fin[3][wid] = Ef; s_fin[4][wid] = Ent; s_fin[5][wid] = Us;
    }
    __syncthreads();
    if (tid == 0) {
        double k = 0, c = 0, tk = 0, ef = 0, en = 0;
        for (int w = 0; w < 8; w++) {
            k += s_fin[0][w]; c += s_fin[1][w]; tk += s_fin[2][w];
            ef += s_fin[3][w]; en += s_fin[4][w];
        }
        double u[EN], mu = 0.0;
        for (int e = 0; e < EN; e++) { u[e] = s_fin[5][e] / (double)BN; mu += u[e]; }
        mu /= (double)EN;
        double var = 0.0;
        for (int e = 0; e < EN; e++) var += (u[e] - mu) * (u[e] - mu);
        var /= (double)(EN - 1);
        double cons = (c > 0.0) ? 0.1 * (k / c) : 0.0;
        double tt = (double)temperature[0] - 1.0;
        double loss = tk / (double)BN
                    + 0.1 * var * (double)(EN * EN)
                    + 0.05 * ef / (double)BN
                    + cons
                    + 0.01 * en / (double)BN
                    + 0.01 * tt * tt;
        out[0] = (float)loss;
    }
}

// ---------------- launch -----------------------------------------------------
extern "C" void kernel_launch(void* const* d_in, const int* in_sizes, int n_in,
                              void* d_out, int out_size) {
    const float* logits  = (const float*)d_in[0];
    const int*   targets = (const int*)d_in[1];
    const float* rp      = (const float*)d_in[2];
    const float* emb     = (const float*)d_in[3];
    const float* temp    = (const float*)d_in[4];
    float* out = (float*)d_out;

    prep_kernel<<<PREP_BLKS, 256>>>(logits, targets, rp, emb);
    pair_kernel<<<GRID_PAIR, 256>>>(temp, out);
}

// round 17
// speedup vs baseline: 1.7321x; 1.0269x over previous
#include <cuda_runtime.h>
#include <cuda_fp16.h>

#define BN 8192
#define EN 8
#define HN 128
#define TS 128
#define NT (BN / TS)                 // 64 tiles per dim
#define NPAIR (NT * (NT + 1) / 2)    // 2080 upper-triangular tile pairs
#define GRID_PAIR 444                // 3 CTAs/SM, one wave
#define PREP_BLKS (BN / 8)           // 1024

// ---------------- device scratch -------------------------------------------
// Fragment-linear fp16 tile images (validated layout).
// One "block" = 512 B = one warp fragment group: lane l holds 16 B at l*16.
//  A image: block (tile, mt 0..7, s16 0..7)  [m16n8k16 A-frag]
//  B image: block (tile, pnt 0..7, s16 0..7) [two n8 B-frags packed]
__device__ __align__(1024) unsigned char g_A[NT * 64 * 512];   // 2 MB
__device__ __align__(1024) unsigned char g_B[NT * 64 * 512];   // 2 MB
// KL operand images, same fragment layouts, single s16:
//   X_i = [logp_i - a_i (8), p_i (8)] (A-frag), Y_j = [p_j (8), logp_j - a_j (8)] (B-frag)
//   X_i . Y_j = -(kl(i,j) + kl(j,i))   (uses sum_e p = 1)
__device__ __align__(1024) unsigned char g_Xf[NT * 8 * 512];   // 256 KB
__device__ __align__(1024) unsigned char g_Yf[NT * 8 * 512];   // 256 KB
// prep per-block partials (written unconditionally -> no zeroing kernel)
__device__ double g_pp_task[PREP_BLKS], g_pp_eff[PREP_BLKS], g_pp_ent[PREP_BLKS];
__device__ float  g_pp_us[PREP_BLKS * EN];
// pair per-CTA partials + never-reset ticket (modular check is replay-safe)
__device__ double g_pair_kl[GRID_PAIR];
__device__ double g_pair_cnt[GRID_PAIR];
__device__ unsigned g_ticket;

// ---------------- PTX helpers ----------------------------------------------
// f16 x f16 -> f16 accumulate: D/C = 2 regs (rows 0-7 | rows 8-15)
__device__ __forceinline__ void mmah(unsigned* d, const unsigned* a, const unsigned* b) {
    asm volatile(
        "mma.sync.aligned.m16n8k16.row.col.f16.f16.f16.f16 "
        "{%0,%1}, {%2,%3,%4,%5}, {%6,%7}, {%0,%1};"
        : "+r"(d[0]), "+r"(d[1])
        : "r"(a[0]), "r"(a[1]), "r"(a[2]), "r"(a[3]), "r"(b[0]), "r"(b[1]));
}
__device__ __forceinline__ unsigned pkhf(float a, float b) {
    return (unsigned)__half_as_ushort(__float2half_rn(a)) |
           ((unsigned)__half_as_ushort(__float2half_rn(b)) << 16);
}
__device__ __forceinline__ float2 h2f(half2 u) { return __half22float2(u); }
__device__ __forceinline__ double wredd(double v) {
#pragma unroll
    for (int o = 16; o > 0; o >>= 1) v += __shfl_xor_sync(0xffffffffu, v, o);
    return v;
}

// ---------------- per-row preprocessing + cheap loss partials ---------------
__global__ __launch_bounds__(256) void prep_kernel(
    const float* __restrict__ logits,
    const int* __restrict__ targets,
    const float* __restrict__ rp,
    const float* __restrict__ emb) {
    int warp = threadIdx.x >> 5, lane = threadIdx.x & 31;
    int row = blockIdx.x * 8 + warp;
    __shared__ float  s_us[EN];
    __shared__ double s_task[8], s_eff[8], s_ent[8];
    if (threadIdx.x < EN) s_us[threadIdx.x] = 0.f;
    __syncthreads();

    // normalize embedding row (float4 per lane = 4 consecutive k-cols)
    float4 v = *(const float4*)(emb + (size_t)row * HN + lane * 4);
    float ss = v.x * v.x + v.y * v.y + v.z * v.z + v.w * v.w;
#pragma unroll
    for (int o = 16; o > 0; o >>= 1) ss += __shfl_xor_sync(0xffffffffu, ss, o);
    float inv = rsqrtf(ss);
    float4 w = make_float4(v.x * inv, v.y * inv, v.z * inv, v.w * inv);

    // write fp16 fragment-linear sim images (A-frag + B-frag)
    {
        int lr   = row & (TS - 1);
        int tile = row >> 7;
        int c0   = lane * 4;                 // cols c0..c0+3, same s16 & khalf
        int s16  = c0 >> 4;
        int kh   = (c0 >> 3) & 1;
        int l0   = ((lr & 7) << 2) | ((c0 & 7) >> 1);   // lanes l0, l0+1
        unsigned w0 = pkhf(w.x, w.y), w1 = pkhf(w.z, w.w);
        int mt = lr >> 4, r8 = (lr >> 3) & 1;
        unsigned baseA = (unsigned)((tile * 64 + mt * 8 + s16) << 9);
        unsigned regA  = (unsigned)(((kh << 1) | r8) << 2);
        *(unsigned*)(g_A + baseA + l0 * 16 + regA)       = w0;
        *(unsigned*)(g_A + baseA + (l0 + 1) * 16 + regA) = w1;
        unsigned baseB = (unsigned)((tile * 64 + mt * 8 + s16) << 9); // pnt==mt
        unsigned innB  = (unsigned)(r8 * 8 + kh * 4);    // ntl==r8
        *(unsigned*)(g_B + baseB + l0 * 16 + innB)       = w0;
        *(unsigned*)(g_B + baseB + (l0 + 1) * 16 + innB) = w1;
    }

    // routing-prob softmax over E=8
    float r = (lane < EN) ? rp[row * EN + lane] : -3.0e38f;
    float m = r;
#pragma unroll
    for (int o = 4; o > 0; o >>= 1) m = fmaxf(m, __shfl_xor_sync(0xffffffffu, m, o));
    float ex = (lane < EN) ? expf(r - m) : 0.f;
    float es = ex;
#pragma unroll
    for (int o = 4; o > 0; o >>= 1) es += __shfl_xor_sync(0xffffffffu, es, o);
    float lse = m + logf(es);
    float lp = r - lse;
    float p  = expf(lp);

    float av  = (lane < EN) ? p * lp : 0.f;
    float evv = (lane < EN && r < 0.1f) ? r : 0.f;
    float nv  = (lane < EN) ? r * logf(r + 1e-8f) : 0.f;
#pragma unroll
    for (int o = 4; o > 0; o >>= 1) {
        av  += __shfl_xor_sync(0xffffffffu, av, o);
        evv += __shfl_xor_sync(0xffffffffu, evv, o);
        nv  += __shfl_xor_sync(0xffffffffu, nv, o);
    }

    // write fragment-linear X/Y KL images (lane e = col-pair index 0..7)
    {
        float l0v = __shfl_sync(0xffffffffu, lp, (lane & 3) * 2);
        float l1v = __shfl_sync(0xffffffffu, lp, (lane & 3) * 2 + 1);
        float p0v = __shfl_sync(0xffffffffu, p,  (lane & 3) * 2);
        float p1v = __shfl_sync(0xffffffffu, p,  (lane & 3) * 2 + 1);
        if (lane < 8) {
            int e = lane;
            unsigned lw = pkhf(l0v - av, l1v - av);
            unsigned pw = pkhf(p0v, p1v);
            unsigned Xw = (e < 4) ? lw : pw;
            unsigned Yw = (e < 4) ? pw : lw;
            int lr = row & (TS - 1), tile = row >> 7;
            int mt = lr >> 4, r8 = (lr >> 3) & 1, kh = e >> 2;
            int lX = ((lr & 7) << 2) | (e & 3);
            unsigned base = (unsigned)((tile * 8 + mt) << 9);
            *(unsigned*)(g_Xf + base + lX * 16 + (((kh << 1) | r8) << 2)) = Xw;
            *(unsigned*)(g_Yf + base + lX * 16 + r8 * 8 + kh * 4)         = Yw;
        }
    }

    if (lane < EN) atomicAdd(&s_us[lane], r);
    if (lane == 0) {
        float l0 = logits[row * 3 + 0], l1 = logits[row * 3 + 1], l2 = logits[row * 3 + 2];
        float mm = fmaxf(l0, fmaxf(l1, l2));
        float lsm = mm + logf(expf(l0 - mm) + expf(l1 - mm) + expf(l2 - mm));
        int t = targets[row];
        float lt = (t == 0) ? l0 : ((t == 1) ? l1 : l2);
        s_task[warp] = (double)(lsm - lt);
        s_eff[warp]  = (double)evv;
        s_ent[warp]  = (double)nv;
    }
    __syncthreads();
    if (threadIdx.x == 0) {
        double a = 0, b = 0, c = 0;
        for (int i = 0; i < 8; i++) { a += s_task[i]; b += s_eff[i]; c += s_ent[i]; }
        g_pp_task[blockIdx.x] = a;
        g_pp_eff[blockIdx.x]  = b;
        g_pp_ent[blockIdx.x]  = c;
    }
    if (threadIdx.x < EN) g_pp_us[blockIdx.x * EN + threadIdx.x] = s_us[threadIdx.x];
}

// ---------------- pair kernel: fp16 acc + half2 SIMD epilogue ---------------
// 256 threads, 3 CTAs/SM. Warp owns 32 m-rows x 64 n-cols, direct-LDG
// fragment mainloop (double-buffered). Epilogue is branch-free half2 SIMD:
//   m2 = hgt2(sim2, 0.8); c2 += m2; one mmah per (mt,nt) -> d2;
//   s2 = hfma2(m2, d2, s2).   D = -(kl(i,j)+kl(j,i)); 0.5x on diagonal.
__global__ __launch_bounds__(256, 3) void pair_kernel(
    const float* __restrict__ temperature, float* __restrict__ out) {
    __shared__ float s_rk[8];
    __shared__ int   s_rc[8];
    __shared__ double s_fin[6][8];
    __shared__ int s_last;

    int tid  = threadIdx.x;
    int wid  = tid >> 5;
    int lane = tid & 31;

    int mt0 = (wid & 3) * 2;        // warp's first m16-tile (of 8)
    int pn0 = (wid >> 2) * 4;       // warp's first pnt block (of 8)
    int mbase = mt0 * 16;
    int nbase = pn0 * 16;

    const half2 thr = __float2half2_rn(0.8f);

    float kls = 0.f;
    int   cnt = 0;

    // decode first tile
    int ti = 0, rem = blockIdx.x;
    while (rem >= NT - ti) { rem -= NT - ti; ti++; }
    int tj = ti + rem;

    for (int t = blockIdx.x; t < NPAIR; t += GRID_PAIR) {
        bool diag = (ti == tj);
        int ti2 = ti, tj2 = tj;
        if (t + GRID_PAIR < NPAIR) {
            int a = 0, r2 = t + GRID_PAIR;
            while (r2 >= NT - a) { r2 -= NT - a; a++; }
            ti2 = a; tj2 = a + r2;
        }

        const uint4* Ab = (const uint4*)g_A + ((size_t)ti << 11) + lane;
        const uint4* Bb = (const uint4*)g_B + ((size_t)tj << 11) + lane;

        unsigned acc[2][8][2];          // f16x2 sim accumulators
#pragma unroll
        for (int a = 0; a < 2; a++)
#pragma unroll
            for (int b = 0; b < 8; b++) { acc[a][b][0] = 0u; acc[a][b][1] = 0u; }

        // double-buffered fragments: [buf][0..1]=A, [buf][2..5]=B
        uint4 fr[2][6];
        fr[0][0] = __ldg(Ab + ((mt0 + 0) * 8 + 0) * 32);
        fr[0][1] = __ldg(Ab + ((mt0 + 1) * 8 + 0) * 32);
        fr[0][2] = __ldg(Bb + ((pn0 + 0) * 8 + 0) * 32);
        fr[0][3] = __ldg(Bb + ((pn0 + 1) * 8 + 0) * 32);
        fr[0][4] = __ldg(Bb + ((pn0 + 2) * 8 + 0) * 32);
        fr[0][5] = __ldg(Bb + ((pn0 + 3) * 8 + 0) * 32);

#pragma unroll
        for (int s = 0; s < 8; s++) {
            int cur = s & 1, nxt = cur ^ 1;
            if (s < 7) {
                fr[nxt][0] = __ldg(Ab + ((mt0 + 0) * 8 + s + 1) * 32);
                fr[nxt][1] = __ldg(Ab + ((mt0 + 1) * 8 + s + 1) * 32);
                fr[nxt][2] = __ldg(Bb + ((pn0 + 0) * 8 + s + 1) * 32);
                fr[nxt][3] = __ldg(Bb + ((pn0 + 1) * 8 + s + 1) * 32);
                fr[nxt][4] = __ldg(Bb + ((pn0 + 2) * 8 + s + 1) * 32);
                fr[nxt][5] = __ldg(Bb + ((pn0 + 3) * 8 + s + 1) * 32);
            }
            const unsigned* af0 = (const unsigned*)&fr[cur][0];
            const unsigned* af1 = (const unsigned*)&fr[cur][1];
#pragma unroll
            for (int pnt = 0; pnt < 4; pnt++) {
                const unsigned* bp = (const unsigned*)&fr[cur][2 + pnt];
                mmah(acc[0][pnt * 2 + 0], af0, bp + 0);
                mmah(acc[0][pnt * 2 + 1], af0, bp + 2);
                mmah(acc[1][pnt * 2 + 0], af1, bp + 0);
                mmah(acc[1][pnt * 2 + 1], af1, bp + 2);
            }
        }

        // ---- epilogue: issue X/Y fragment loads first (latency cover) ----
        const uint4* Xb = (const uint4*)g_Xf + ((size_t)ti << 8) + lane;
        const uint4* Yb = (const uint4*)g_Yf + ((size_t)tj << 8) + lane;
        uint4 xa[2], yb[4];
        xa[0] = __ldg(Xb + (mt0 + 0) * 32);
        xa[1] = __ldg(Xb + (mt0 + 1) * 32);
        yb[0] = __ldg(Yb + (pn0 + 0) * 32);
        yb[1] = __ldg(Yb + (pn0 + 1) * 32);
        yb[2] = __ldg(Yb + (pn0 + 2) * 32);
        yb[3] = __ldg(Yb + (pn0 + 3) * 32);

        // ---- fused mask + masked-KL in half2 SIMD ----
        half2 s2 = __float2half2_rn(0.f);
        half2 c2 = __float2half2_rn(0.f);
#pragma unroll
        for (int mt = 0; mt < 2; mt++) {
            const unsigned* xf = (const unsigned*)&xa[mt];
#pragma unroll
            for (int pnt = 0; pnt < 4; pnt++) {
#pragma unroll
                for (int ntl = 0; ntl < 2; ntl++) {
                    int nt = pnt * 2 + ntl;
                    unsigned d[2] = { 0u, 0u };      // KL mma result (fresh)
                    mmah(d, xf, ((const unsigned*)&yb[pnt]) + 2 * ntl);
#pragma unroll
                    for (int rr = 0; rr < 2; rr++) {
                        half2 sim2 = *reinterpret_cast<const half2*>(&acc[mt][nt][rr]);
                        half2 m2 = __hgt2(sim2, thr);
                        if (diag) {                  // eye exclusion (rare tiles)
                            int il  = mbase + mt * 16 + rr * 8 + (lane >> 2);
                            int jl0 = nbase + nt * 8 + (lane & 3) * 2;
                            half2 e2 = __floats2half2_rn(il != jl0 ? 1.f : 0.f,
                                                         il != jl0 + 1 ? 1.f : 0.f);
                            m2 = __hmul2(m2, e2);
                        }
                        c2 = __hadd2(c2, m2);
                        half2 d2 = *reinterpret_cast<const half2*>(&d[rr]);
                        s2 = __hfma2(m2, d2, s2);
                    }
                }
            }
        }
        float2 fs = h2f(s2), fc = h2f(c2);
        float S = fs.x + fs.y;
        float C = fc.x + fc.y;
        cnt += __float2int_rn(C) * (diag ? 1 : 2);
        kls -= diag ? 0.5f * S : S;    // D = -(kl sum); diag double-counts pairs

        ti = ti2; tj = tj2;
    }

    // ---- flush per-CTA partial ----
#pragma unroll
    for (int o = 16; o > 0; o >>= 1) {
        kls += __shfl_xor_sync(0xffffffffu, kls, o);
        cnt += __shfl_xor_sync(0xffffffffu, cnt, o);
    }
    if (lane == 0) { s_rk[wid] = kls; s_rc[wid] = cnt; }
    __syncthreads();
    if (tid == 0) {
        double K = 0, C = 0;
        for (int w = 0; w < 8; w++) { K += (double)s_rk[w]; C += (double)s_rc[w]; }
        g_pair_kl[blockIdx.x]  = K;
        g_pair_cnt[blockIdx.x] = C;
        __threadfence();
        unsigned old = atomicAdd(&g_ticket, 1u);
        s_last = ((old % GRID_PAIR) == GRID_PAIR - 1) ? 1 : 0;
    }
    __syncthreads();
    if (!s_last) return;
    __threadfence();

    // ---- last CTA: reduce all partials, compute final loss ----
    double K = 0, C = 0, Tk = 0, Ef = 0, Ent = 0;
    for (int i = tid; i < GRID_PAIR; i += 256) { K += g_pair_kl[i]; C += g_pair_cnt[i]; }
    for (int i = tid; i < PREP_BLKS; i += 256) {
        Tk += g_pp_task[i]; Ef += g_pp_eff[i]; Ent += g_pp_ent[i];
    }
    double Us = 0;                     // warp w reduces expert w
    for (int i = lane; i < PREP_BLKS; i += 32) Us += (double)g_pp_us[i * EN + wid];

    K = wredd(K); C = wredd(C); Tk = wredd(Tk); Ef = wredd(Ef); Ent = wredd(Ent);
    Us = wredd(Us);
    if (lane == 0) {
        s_fin[0][wid] = K;  s_fin[1][wid] = C;  s_fin[2][wid] = Tk;
        s_fin[3][wid] = Ef; s_fin[4][wid] = Ent; s_fin[5][wid] = Us;
    }
    __syncthreads();
    if (tid == 0) {
        double k = 0, c = 0, tk = 0, ef = 0, en = 0;
        for (int w = 0; w < 8; w++) {
            k += s_fin[0][w]; c += s_fin[1][w]; tk += s_fin[2][w];
            ef += s_fin[3][w]; en += s_fin[4][w];
        }
        double u[EN], mu = 0.0;
        for (int e = 0; e < EN; e++) { u[e] = s_fin[5][e] / (double)BN; mu += u[e]; }
        mu /= (double)EN;
        double var = 0.0;
        for (int e = 0; e < EN; e++) var += (u[e] - mu) * (u[e] - mu);
        var /= (double)(EN - 1);
        double cons = (c > 0.0) ? 0.1 * (k / c) : 0.0;
        double tt = (double)temperature[0] - 1.0;
        double loss = tk / (double)BN
                    + 0.1 * var * (double)(EN * EN)
                    + 0.05 * ef / (double)BN
                    + cons
                    + 0.01 * en / (double)BN
                    + 0.01 * tt * tt;
        out[0] = (float)loss;
    }
}

// ---------------- launch -----------------------------------------------------
extern "C" void kernel_launch(void* const* d_in, const int* in_sizes, int n_in,
                              void* d_out, int out_size) {
    const float* logits  = (const float*)d_in[0];
    const int*   targets = (const int*)d_in[1];
    const float* rp      = (const float*)d_in[2];
    const float* emb     = (const float*)d_in[3];
    const float* temp    = (const float*)d_in[4];
    float* out = (float*)d_out;

    prep_kernel<<<PREP_BLKS, 256>>>(logits, targets, rp, emb);
    pair_kernel<<<GRID_PAIR, 256>>>(temp, out);
}